// round 1
// baseline (speedup 1.0000x reference)
#include <cuda_runtime.h>
#include <math_constants.h>

#define NROWS 16384
#define DIMS  256
#define NEMB  8192

// Output layout (float32, reference return order, flattened+concatenated)
#define OFF_Q    0
#define OFF_DIFF 4194304
#define OFF_IND  4194305
#define OFF_EMB  4210689
#define OFF_NCS  6307841
#define OFF_AVG  6316033

// Scratch (no cudaMalloc allowed)
__device__ float g_enorm[NEMB];
__device__ int   g_argmin[NROWS];
__device__ int   g_count[NEMB];
__device__ float g_n;

// ---------------------------------------------------------------------------
// A: init — zero counters, diff, n; seed new_embedding_avg with 0.99*avg
// ---------------------------------------------------------------------------
__global__ void k_init(const float* __restrict__ eavg, float* __restrict__ out) {
    int i = blockIdx.x * blockDim.x + threadIdx.x;
    if (i < DIMS * NEMB) out[OFF_AVG + i] = 0.99f * eavg[i];
    if (i < NEMB) g_count[i] = 0;
    if (i == 0) { g_n = 0.0f; out[OFF_DIFF] = 0.0f; }
}

// ---------------------------------------------------------------------------
// B: per-code squared norms ||e_j||^2
// ---------------------------------------------------------------------------
__global__ void k_enorm(const float* __restrict__ E) {
    int j = blockIdx.x * blockDim.x + threadIdx.x;
    if (j >= NEMB) return;
    float s = 0.0f;
#pragma unroll 8
    for (int k = 0; k < DIMS; k++) {
        float e = E[(size_t)k * NEMB + j];
        s = fmaf(e, e, s);
    }
    g_enorm[j] = s;
}

// ---------------------------------------------------------------------------
// C: fused fp32 GEMM + argmin.  BM=32 rows x BN=64 codes per CTA (256 thr).
//    dist_j = ||e_j||^2 - 2 x.e_j  (row-constant ||x||^2 dropped)
// ---------------------------------------------------------------------------
#define BM 32
#define BN 64
#define BK 64

__global__ __launch_bounds__(256) void k_argmin(
    const float* __restrict__ z, const float* __restrict__ E,
    float* __restrict__ out)
{
    __shared__ float Xs[BM][DIMS];   // 32 KB
    __shared__ float Es[BK][BN];     // 16 KB

    const int tid = threadIdx.x;
    const int tx  = tid & 15;        // code group: 4 codes each
    const int ty  = tid >> 4;        // row group : 2 rows each
    const int row0 = blockIdx.x * BM;

    // load X slab (contiguous both sides)
    {
        const float4* zg = (const float4*)(z + (size_t)row0 * DIMS);
        float4* xs = (float4*)(&Xs[0][0]);
        for (int i = tid; i < BM * DIMS / 4; i += 256) xs[i] = zg[i];
    }
    __syncthreads();

    float bestv0 = CUDART_INF_F, bestv1 = CUDART_INF_F;
    int   bestj0 = 0, bestj1 = 0;
    const int r0 = ty * 2, r1 = ty * 2 + 1;

    for (int jt = 0; jt < NEMB; jt += BN) {
        float acc[2][4] = {{0,0,0,0},{0,0,0,0}};
        for (int kt = 0; kt < DIMS; kt += BK) {
            // stage E chunk [BK x BN]
            {
                const int c4 = tid & 15;
                const int rb = tid >> 4;
#pragma unroll
                for (int rr = 0; rr < 4; rr++) {
                    int r = rb + rr * 16;
                    float4 v = *(const float4*)(E + (size_t)(kt + r) * NEMB + jt + c4 * 4);
                    *(float4*)&Es[r][c4 * 4] = v;
                }
            }
            __syncthreads();
#pragma unroll 16
            for (int kk = 0; kk < BK; kk++) {
                float4 e = *(const float4*)&Es[kk][tx * 4];
                float x0 = Xs[r0][kt + kk];
                float x1 = Xs[r1][kt + kk];
                acc[0][0] = fmaf(x0, e.x, acc[0][0]);
                acc[0][1] = fmaf(x0, e.y, acc[0][1]);
                acc[0][2] = fmaf(x0, e.z, acc[0][2]);
                acc[0][3] = fmaf(x0, e.w, acc[0][3]);
                acc[1][0] = fmaf(x1, e.x, acc[1][0]);
                acc[1][1] = fmaf(x1, e.y, acc[1][1]);
                acc[1][2] = fmaf(x1, e.z, acc[1][2]);
                acc[1][3] = fmaf(x1, e.w, acc[1][3]);
            }
            __syncthreads();
        }
        // running argmin (ascending code index keeps lowest index on ties)
#pragma unroll
        for (int j = 0; j < 4; j++) {
            int code = jt + tx * 4 + j;
            float en = __ldg(&g_enorm[code]);
            float d0 = fmaf(-2.0f, acc[0][j], en);
            float d1 = fmaf(-2.0f, acc[1][j], en);
            if (d0 < bestv0) { bestv0 = d0; bestj0 = code; }
            if (d1 < bestv1) { bestv1 = d1; bestj1 = code; }
        }
    }

    // reduce across the 16 code-lanes (same ty); tie -> lower index
#pragma unroll
    for (int off = 8; off; off >>= 1) {
        float v0 = __shfl_down_sync(0xffffffffu, bestv0, off, 16);
        int   j0 = __shfl_down_sync(0xffffffffu, bestj0, off, 16);
        if (v0 < bestv0 || (v0 == bestv0 && j0 < bestj0)) { bestv0 = v0; bestj0 = j0; }
        float v1 = __shfl_down_sync(0xffffffffu, bestv1, off, 16);
        int   j1 = __shfl_down_sync(0xffffffffu, bestj1, off, 16);
        if (v1 < bestv1 || (v1 == bestv1 && j1 < bestj1)) { bestv1 = v1; bestj1 = j1; }
    }
    if (tx == 0) {
        int rr0 = row0 + r0, rr1 = row0 + r1;
        g_argmin[rr0] = bestj0;  out[OFF_IND + rr0] = (float)bestj0;
        g_argmin[rr1] = bestj1;  out[OFF_IND + rr1] = (float)bestj1;
    }
}

// ---------------------------------------------------------------------------
// D: gather quantize, diff partial sums, scatter segment sums (atomics).
//    One warp per row; 8 rows per CTA.
// ---------------------------------------------------------------------------
__global__ __launch_bounds__(256) void k_gather(
    const float* __restrict__ z, const float* __restrict__ E,
    float* __restrict__ out)
{
    __shared__ float warpsum[8];
    const int warp = threadIdx.x >> 5, lane = threadIdx.x & 31;
    const int r = blockIdx.x * 8 + warp;
    const int j = g_argmin[r];

    float ss = 0.0f;
#pragma unroll
    for (int it = 0; it < 8; it++) {
        int d = lane + it * 32;
        float e  = E[(size_t)d * NEMB + j];
        float zv = z[(size_t)r * DIMS + d];
        float qd = e - zv;
        out[OFF_Q + (size_t)r * DIMS + d] = zv + qd;   // quantize_st == quantize
        ss = fmaf(qd, qd, ss);
        atomicAdd(&out[OFF_AVG + (size_t)d * NEMB + j], 0.01f * zv);
    }
    if (lane == 0) atomicAdd(&g_count[j], 1);
#pragma unroll
    for (int o = 16; o; o >>= 1) ss += __shfl_down_sync(0xffffffffu, ss, o);
    if (lane == 0) warpsum[warp] = ss;
    __syncthreads();
    if (threadIdx.x == 0) {
        float t = 0.0f;
#pragma unroll
        for (int w = 0; w < 8; w++) t += warpsum[w];
        atomicAdd(&out[OFF_DIFF], t);
    }
}

// ---------------------------------------------------------------------------
// E: new_cluster_size + global n reduction
// ---------------------------------------------------------------------------
__global__ void k_ncs(const float* __restrict__ cs, float* __restrict__ out) {
    __shared__ float sh[256];
    int j = blockIdx.x * 256 + threadIdx.x;
    float v = cs[j] * 0.99f + 0.01f * (float)g_count[j];
    out[OFF_NCS + j] = v;
    sh[threadIdx.x] = v;
    __syncthreads();
    for (int s = 128; s; s >>= 1) {
        if (threadIdx.x < s) sh[threadIdx.x] += sh[threadIdx.x + s];
        __syncthreads();
    }
    if (threadIdx.x == 0) atomicAdd(&g_n, sh[0]);
}

// ---------------------------------------------------------------------------
// F: new_embedding = avg / smoothed; finalize diff mean
// ---------------------------------------------------------------------------
__global__ void k_final(float* __restrict__ out) {
    int i = blockIdx.x * blockDim.x + threadIdx.x;
    if (i == 0) out[OFF_DIFF] *= (1.0f / 4194304.0f);
    if (i >= DIMS * NEMB) return;
    float n = g_n;
    int j = i & (NEMB - 1);
    float ncs = out[OFF_NCS + j];
    float smoothed = (ncs + 1e-5f) / (n + (float)NEMB * 1e-5f) * n;
    out[OFF_EMB + i] = out[OFF_AVG + i] / smoothed;
}

// ---------------------------------------------------------------------------
extern "C" void kernel_launch(void* const* d_in, const int* in_sizes, int n_in,
                              void* d_out, int out_size) {
    const float* z    = (const float*)d_in[0];   // [16,32,32,256]
    const float* E    = (const float*)d_in[1];   // [256, 8192]
    const float* cs   = (const float*)d_in[2];   // [8192]
    const float* eavg = (const float*)d_in[3];   // [256, 8192]
    float* out = (float*)d_out;

    k_init  <<<(DIMS * NEMB + 255) / 256, 256>>>(eavg, out);
    k_enorm <<<NEMB / 256, 256>>>(E);
    k_argmin<<<NROWS / BM, 256>>>(z, E, out);
    k_gather<<<NROWS / 8, 256>>>(z, E, out);
    k_ncs   <<<NEMB / 256, 256>>>(cs, out);
    k_final <<<(DIMS * NEMB + 255) / 256, 256>>>(out);
}

// round 2
// speedup vs baseline: 1.6769x; 1.6769x over previous
#include <cuda_runtime.h>
#include <math_constants.h>
#include <stdint.h>

#define NROWS 16384
#define DIMS  256
#define NEMB  8192

// Output layout (float32, reference return order, flattened+concatenated)
#define OFF_Q    0
#define OFF_DIFF 4194304
#define OFF_IND  4194305
#define OFF_EMB  4210689
#define OFF_NCS  6307841
#define OFF_AVG  6316033

// Scratch (no cudaMalloc allowed)
__device__ float g_enorm[NEMB];
__device__ int   g_argmin[NROWS];
__device__ int   g_count[NEMB];
__device__ float g_n;

typedef unsigned long long ull;

__device__ __forceinline__ ull pack2(float lo, float hi) {
    ull r; asm("mov.b64 %0, {%1, %2};" : "=l"(r) : "f"(lo), "f"(hi)); return r;
}
__device__ __forceinline__ void unpack2(ull v, float& lo, float& hi) {
    asm("mov.b64 {%0, %1}, %2;" : "=f"(lo), "=f"(hi) : "l"(v));
}
__device__ __forceinline__ ull fma2(ull a, ull b, ull c) {
    ull d; asm("fma.rn.f32x2 %0, %1, %2, %3;" : "=l"(d) : "l"(a), "l"(b), "l"(c)); return d;
}
__device__ __forceinline__ void cp_async16(uint32_t s, const void* g) {
    asm volatile("cp.async.ca.shared.global [%0], [%1], 16;" :: "r"(s), "l"(g));
}

// ---------------------------------------------------------------------------
// A: init — zero counters, diff, n; seed new_embedding_avg with 0.99*avg
// ---------------------------------------------------------------------------
__global__ void k_init(const float* __restrict__ eavg, float* __restrict__ out) {
    int i = blockIdx.x * blockDim.x + threadIdx.x;
    if (i < DIMS * NEMB) out[OFF_AVG + i] = 0.99f * eavg[i];
    if (i < NEMB) g_count[i] = 0;
    if (i == 0) { g_n = 0.0f; out[OFF_DIFF] = 0.0f; }
}

// ---------------------------------------------------------------------------
// B: per-code squared norms ||e_j||^2
// ---------------------------------------------------------------------------
__global__ void k_enorm(const float* __restrict__ E) {
    int j = blockIdx.x * blockDim.x + threadIdx.x;
    if (j >= NEMB) return;
    float s = 0.0f;
#pragma unroll 8
    for (int k = 0; k < DIMS; k++) {
        float e = E[(size_t)k * NEMB + j];
        s = fmaf(e, e, s);
    }
    g_enorm[j] = s;
}

// ---------------------------------------------------------------------------
// C: fused f32x2 GEMM + argmin. BM=128 x BN=64 per 256-thread CTA.
//    Per thread: 4 rows x 8 codes (codes packed pairwise in f32x2 lanes).
//    X resident in smem (padded stride 258); E double-buffered via cp.async.
//    dist_j = ||e_j||^2 - 2 x.e_j  (row-constant ||x||^2 dropped)
// ---------------------------------------------------------------------------
#define BM 128
#define BN 64
#define BK 64
#define XS_STRIDE 258
#define XS_FLOATS (BM * XS_STRIDE)          // 33024 floats
#define ES_FLOATS (BK * BN)                 // 4096 floats per buffer
#define ARG_SMEM_BYTES ((XS_FLOATS + 2 * ES_FLOATS) * 4)   // 164864

__global__ __launch_bounds__(256) void k_argmin2(
    const float* __restrict__ z, const float* __restrict__ E,
    float* __restrict__ out)
{
    extern __shared__ float smem[];
    float* Xs = smem;                       // [128][258]
    float* Es = smem + XS_FLOATS;           // [2][64][64]

    const int tid = threadIdx.x;
    const int tx  = tid & 7;                // 8 code-columns
    const int ty  = tid >> 3;               // 32 row-groups (4 rows each)
    const int row0 = blockIdx.x * BM;

    const uint32_t es_base = (uint32_t)__cvta_generic_to_shared(Es);

    // stage chunk cc (jt = (cc>>2)*64, kt = (cc&3)*64) into buffer buf
    auto fill = [&](int cc, int buf) {
        const int jt = (cc >> 2) * BN;
        const int kt = (cc & 3) * BK;
#pragma unroll
        for (int i = 0; i < 4; i++) {
            int idx = tid + i * 256;        // 1024 x 16B chunks
            int k = idx >> 4, off = idx & 15;
            const float* g = E + (size_t)(kt + k) * NEMB + jt + off * 4;
            cp_async16(es_base + (uint32_t)(buf * ES_FLOATS + k * BN + off * 4) * 4, g);
        }
        asm volatile("cp.async.commit_group;");
    };

    fill(0, 0);   // overlap first E stage with X load

    // load X slab (128 x 256) into padded smem; float4 LDG -> 2x float2 STS
    {
        const float4* zg = (const float4*)(z + (size_t)row0 * DIMS);
        for (int i = tid; i < BM * (DIMS / 4); i += 256) {
            int r = i >> 6, c4 = i & 63;
            float4 v = zg[(size_t)r * 64 + c4];
            float* d = Xs + r * XS_STRIDE + c4 * 4;
            *(float2*)d       = make_float2(v.x, v.y);
            *(float2*)(d + 2) = make_float2(v.z, v.w);
        }
    }
    __syncthreads();

    const ull neg2 = pack2(-2.0f, -2.0f);
    float bestv[4] = {CUDART_INF_F, CUDART_INF_F, CUDART_INF_F, CUDART_INF_F};
    int   bestj[4] = {0, 0, 0, 0};
    ull acc[4][4];  // [row r][code-pair p], persists across the 4 kt chunks

    for (int cc = 0; cc < 512; cc++) {
        const int buf = cc & 1;
        const int jt  = (cc >> 2) * BN;
        const int kt  = (cc & 3) * BK;

        if (cc + 1 < 512) {
            fill(cc + 1, buf ^ 1);
            asm volatile("cp.async.wait_group 1;");
        } else {
            asm volatile("cp.async.wait_group 0;");
        }
        __syncthreads();

        if ((cc & 3) == 0) {
#pragma unroll
            for (int r = 0; r < 4; r++)
#pragma unroll
                for (int p = 0; p < 4; p++) acc[r][p] = 0ull;
        }

        const float* Eb = Es + buf * ES_FLOATS;
#pragma unroll 8
        for (int ki = 0; ki < BK / 2; ki++) {
            // x: float2 along k (conflict-free, 8-way broadcast), pack (x,x)
            ull xx0[4], xx1[4];
#pragma unroll
            for (int r = 0; r < 4; r++) {
                float2 xv = *(const float2*)&Xs[(ty * 4 + r) * XS_STRIDE + kt + 2 * ki];
                xx0[r] = pack2(xv.x, xv.x);
                xx1[r] = pack2(xv.y, xv.y);
            }
#pragma unroll
            for (int p = 0; p < 4; p++) {
                const int cbase = 2 * tx + 16 * p;
                ull ea = *(const ull*)&Eb[(2 * ki)     * BN + cbase];
                ull eb = *(const ull*)&Eb[(2 * ki + 1) * BN + cbase];
#pragma unroll
                for (int r = 0; r < 4; r++) {
                    acc[r][p] = fma2(xx0[r], ea, acc[r][p]);
                    acc[r][p] = fma2(xx1[r], eb, acc[r][p]);
                }
            }
        }
        __syncthreads();   // compute done before this buffer is refilled

        if ((cc & 3) == 3) {
            // epilogue for this jt tile: dist = ||e||^2 - 2 dot; running argmin
#pragma unroll
            for (int p = 0; p < 4; p++) {
                const int c0 = jt + 2 * tx + 16 * p;
                float2 en = *(const float2*)&g_enorm[c0];
                ull en2 = pack2(en.x, en.y);
#pragma unroll
                for (int r = 0; r < 4; r++) {
                    ull d2 = fma2(neg2, acc[r][p], en2);
                    float d0, d1; unpack2(d2, d0, d1);
                    if (d0 < bestv[r]) { bestv[r] = d0; bestj[r] = c0; }
                    if (d1 < bestv[r]) { bestv[r] = d1; bestj[r] = c0 + 1; }
                }
            }
        }
    }

    // reduce across the 8 code-lanes (groups of 8 consecutive lanes); tie -> lower idx
#pragma unroll
    for (int r = 0; r < 4; r++) {
        float v = bestv[r]; int j = bestj[r];
#pragma unroll
        for (int o = 4; o; o >>= 1) {
            float v2 = __shfl_down_sync(0xffffffffu, v, o, 8);
            int   j2 = __shfl_down_sync(0xffffffffu, j, o, 8);
            if (v2 < v || (v2 == v && j2 < j)) { v = v2; j = j2; }
        }
        if (tx == 0) {
            int row = row0 + ty * 4 + r;
            g_argmin[row] = j;
            out[OFF_IND + row] = (float)j;
        }
    }
}

// ---------------------------------------------------------------------------
// D: gather quantize, diff partial sums, scatter segment sums (atomics).
// ---------------------------------------------------------------------------
__global__ __launch_bounds__(256) void k_gather(
    const float* __restrict__ z, const float* __restrict__ E,
    float* __restrict__ out)
{
    __shared__ float warpsum[8];
    const int warp = threadIdx.x >> 5, lane = threadIdx.x & 31;
    const int r = blockIdx.x * 8 + warp;
    const int j = g_argmin[r];

    float ss = 0.0f;
#pragma unroll
    for (int it = 0; it < 8; it++) {
        int d = lane + it * 32;
        float e  = E[(size_t)d * NEMB + j];
        float zv = z[(size_t)r * DIMS + d];
        float qd = e - zv;
        out[OFF_Q + (size_t)r * DIMS + d] = zv + qd;
        ss = fmaf(qd, qd, ss);
        atomicAdd(&out[OFF_AVG + (size_t)d * NEMB + j], 0.01f * zv);
    }
    if (lane == 0) atomicAdd(&g_count[j], 1);
#pragma unroll
    for (int o = 16; o; o >>= 1) ss += __shfl_down_sync(0xffffffffu, ss, o);
    if (lane == 0) warpsum[warp] = ss;
    __syncthreads();
    if (threadIdx.x == 0) {
        float t = 0.0f;
#pragma unroll
        for (int w = 0; w < 8; w++) t += warpsum[w];
        atomicAdd(&out[OFF_DIFF], t);
    }
}

// ---------------------------------------------------------------------------
// E: new_cluster_size + global n reduction
// ---------------------------------------------------------------------------
__global__ void k_ncs(const float* __restrict__ cs, float* __restrict__ out) {
    __shared__ float sh[256];
    int j = blockIdx.x * 256 + threadIdx.x;
    float v = cs[j] * 0.99f + 0.01f * (float)g_count[j];
    out[OFF_NCS + j] = v;
    sh[threadIdx.x] = v;
    __syncthreads();
    for (int s = 128; s; s >>= 1) {
        if (threadIdx.x < s) sh[threadIdx.x] += sh[threadIdx.x + s];
        __syncthreads();
    }
    if (threadIdx.x == 0) atomicAdd(&g_n, sh[0]);
}

// ---------------------------------------------------------------------------
// F: new_embedding = avg / smoothed; finalize diff mean
// ---------------------------------------------------------------------------
__global__ void k_final(float* __restrict__ out) {
    int i = blockIdx.x * blockDim.x + threadIdx.x;
    if (i == 0) out[OFF_DIFF] *= (1.0f / 4194304.0f);
    if (i >= DIMS * NEMB) return;
    float n = g_n;
    int j = i & (NEMB - 1);
    float ncs = out[OFF_NCS + j];
    float smoothed = (ncs + 1e-5f) / (n + (float)NEMB * 1e-5f) * n;
    out[OFF_EMB + i] = out[OFF_AVG + i] / smoothed;
}

// ---------------------------------------------------------------------------
extern "C" void kernel_launch(void* const* d_in, const int* in_sizes, int n_in,
                              void* d_out, int out_size) {
    const float* z    = (const float*)d_in[0];   // [16,32,32,256]
    const float* E    = (const float*)d_in[1];   // [256, 8192]
    const float* cs   = (const float*)d_in[2];   // [8192]
    const float* eavg = (const float*)d_in[3];   // [256, 8192]
    float* out = (float*)d_out;

    cudaFuncSetAttribute(k_argmin2, cudaFuncAttributeMaxDynamicSharedMemorySize,
                         ARG_SMEM_BYTES);

    k_init   <<<(DIMS * NEMB + 255) / 256, 256>>>(eavg, out);
    k_enorm  <<<NEMB / 256, 256>>>(E);
    k_argmin2<<<NROWS / BM, 256, ARG_SMEM_BYTES>>>(z, E, out);
    k_gather <<<NROWS / 8, 256>>>(z, E, out);
    k_ncs    <<<NEMB / 256, 256>>>(cs, out);
    k_final  <<<(DIMS * NEMB + 255) / 256, 256>>>(out);
}

// round 4
// speedup vs baseline: 3.7648x; 2.2451x over previous
#include <cuda_runtime.h>
#include <cuda_bf16.h>
#include <math_constants.h>
#include <stdint.h>

#define NROWS 16384
#define DIMS  256
#define NEMB  8192

// Output layout (float32, reference return order, flattened+concatenated)
#define OFF_Q    0
#define OFF_DIFF 4194304
#define OFF_IND  4194305
#define OFF_EMB  4210689
#define OFF_NCS  6307841
#define OFF_AVG  6316033

// Scratch (no cudaMalloc allowed)
__device__ float          g_enorm[NEMB];
__device__ int            g_arg2[2 * NROWS];       // top-2 candidates per row
__device__ int            g_count[NEMB];
__device__ float          g_n;
__device__ __nv_bfloat16  g_zhi[NROWS * DIMS];     // [row][k]
__device__ __nv_bfloat16  g_zlo[NROWS * DIMS];
__device__ __nv_bfloat16  g_ehi[NEMB * DIMS];      // [code][k] (transposed)
__device__ __nv_bfloat16  g_elo[NEMB * DIMS];

// ---------------------------------------------------------------------------
// PTX helpers — baseline sm_80+ features only (NO tcgen05: ptxas target is
// compute_103 without the 'a' suffix and rejects arch-accelerated features).
// ---------------------------------------------------------------------------
__device__ __forceinline__ uint32_t smem_u32(const void* p) {
    uint32_t a;
    asm("{ .reg .u64 t; cvta.to.shared.u64 t, %1; cvt.u32.u64 %0, t; }" : "=r"(a) : "l"(p));
    return a;
}
__device__ __forceinline__ void cp_async16(uint32_t s, const void* g) {
    asm volatile("cp.async.ca.shared.global [%0], [%1], 16;" :: "r"(s), "l"(g));
}
#define CP_COMMIT() asm volatile("cp.async.commit_group;")
#define CP_WAIT0()  asm volatile("cp.async.wait_group 0;")
#define CP_WAIT1()  asm volatile("cp.async.wait_group 1;")

__device__ __forceinline__ void ldsm_x4(uint32_t* r, uint32_t a) {
    asm volatile("ldmatrix.sync.aligned.m8n8.x4.shared.b16 {%0,%1,%2,%3}, [%4];"
                 : "=r"(r[0]), "=r"(r[1]), "=r"(r[2]), "=r"(r[3]) : "r"(a));
}
__device__ __forceinline__ void ldsm_x2(uint32_t* r, uint32_t a) {
    asm volatile("ldmatrix.sync.aligned.m8n8.x2.shared.b16 {%0,%1}, [%2];"
                 : "=r"(r[0]), "=r"(r[1]) : "r"(a));
}
__device__ __forceinline__ void mma16816(float* d, const uint32_t* a, const uint32_t* b) {
    asm volatile("mma.sync.aligned.m16n8k16.row.col.f32.bf16.bf16.f32 "
                 "{%0,%1,%2,%3}, {%4,%5,%6,%7}, {%8,%9}, {%0,%1,%2,%3};"
                 : "+f"(d[0]), "+f"(d[1]), "+f"(d[2]), "+f"(d[3])
                 : "r"(a[0]), "r"(a[1]), "r"(a[2]), "r"(a[3]), "r"(b[0]), "r"(b[1]));
}

// merge sorted top-2 list (w0,i0,w1,i1) into (v0,j0,v1,j1)
__device__ __forceinline__ void top2_merge(float& v0, int& j0, float& v1, int& j1,
                                           float w0, int i0, float w1, int i1) {
    if (w0 < v0) {
        float nv1 = (v0 < w1) ? v0 : w1;
        int   nj1 = (v0 < w1) ? j0 : i1;
        v1 = nv1; j1 = nj1; v0 = w0; j0 = i0;
    } else if (w0 < v1) {
        v1 = w0; j1 = i0;
    }
}

// ---------------------------------------------------------------------------
// A: init — zero counters, diff, n; seed new_embedding_avg with 0.99*avg
// ---------------------------------------------------------------------------
__global__ void k_init(const float* __restrict__ eavg, float* __restrict__ out) {
    int i = blockIdx.x * blockDim.x + threadIdx.x;
    if (i < DIMS * NEMB) out[OFF_AVG + i] = 0.99f * eavg[i];
    if (i < NEMB) g_count[i] = 0;
    if (i == 0) { g_n = 0.0f; out[OFF_DIFF] = 0.0f; }
}

// ---------------------------------------------------------------------------
// B: per-code squared norms ||e_j||^2
// ---------------------------------------------------------------------------
__global__ void k_enorm(const float* __restrict__ E) {
    int j = blockIdx.x * blockDim.x + threadIdx.x;
    if (j >= NEMB) return;
    float s = 0.0f;
#pragma unroll 8
    for (int k = 0; k < DIMS; k++) {
        float e = E[(size_t)k * NEMB + j];
        s = fmaf(e, e, s);
    }
    g_enorm[j] = s;
}

// ---------------------------------------------------------------------------
// B2: split z into bf16 hi/lo ([row][k] layout)
// ---------------------------------------------------------------------------
__global__ void k_split_z(const float* __restrict__ z) {
    int i = blockIdx.x * blockDim.x + threadIdx.x;
    float x = z[i];
    __nv_bfloat16 h = __float2bfloat16(x);
    g_zhi[i] = h;
    g_zlo[i] = __float2bfloat16(x - __bfloat162float(h));
}

// ---------------------------------------------------------------------------
// B3: split+transpose E: [k][j] fp32 -> [j][k] bf16 hi/lo (32x32 smem tiles)
// ---------------------------------------------------------------------------
__global__ void k_split_eT(const float* __restrict__ E) {
    __shared__ float t[32][33];
    int j0 = blockIdx.x * 32, k0 = blockIdx.y * 32;
    int tx = threadIdx.x, ty = threadIdx.y;   // (32, 8)
#pragma unroll
    for (int s = 0; s < 32; s += 8)
        t[ty + s][tx] = E[(size_t)(k0 + ty + s) * NEMB + j0 + tx];
    __syncthreads();
#pragma unroll
    for (int s = 0; s < 32; s += 8) {
        float x = t[tx][ty + s];
        __nv_bfloat16 h = __float2bfloat16(x);
        size_t o = (size_t)(j0 + ty + s) * DIMS + k0 + tx;
        g_ehi[o] = h;
        g_elo[o] = __float2bfloat16(x - __bfloat162float(h));
    }
}

// ---------------------------------------------------------------------------
// C: split-bf16 mma.sync GEMM + fused top-2 argmin.
//    CTA: 128 rows, 8 warps (2m x 4n), warp tile 64x32.
//    A (hi+lo, K=256) resident in smem; B double-buffered, 64-k chunks.
//    16B-chunk XOR swizzle: chunk c of row r stored at c ^ (r&7).
// ---------------------------------------------------------------------------
#define SM_A     0          // 8 planes of 16 KB: [split][kc]
#define SM_B     131072     // 4 planes: [buf][split]
#define SM_RED   131072     // reused for final top-2 merge
#define SMEM_TOTAL 196608

__global__ __launch_bounds__(256) void k_argmin_mma() {
    extern __shared__ char smem[];
    const uint32_t sb = smem_u32(smem);
    const int tid = threadIdx.x, wid = tid >> 5, l = tid & 31;
    const int wm = wid >> 2, wn = wid & 3;
    const int row0 = blockIdx.x * 128;

    // stage resident A (hi+lo, 4 k-chunks): 8192 x 16B  (group 0)
    {
#pragma unroll
        for (int t = 0; t < 32; t++) {
            int i = tid + t * 256;
            int s = i >> 12, rem = i & 4095;
            int kc = rem >> 10, r = (rem >> 3) & 127, c = rem & 7;
            const __nv_bfloat16* g = (s ? g_zlo : g_zhi)
                + (size_t)(row0 + r) * DIMS + kc * 64 + c * 8;
            cp_async16(sb + SM_A + (s * 4 + kc) * 16384 + r * 128 + ((c ^ (r & 7)) << 4), g);
        }
        CP_COMMIT();
    }

    auto stageB = [&](int q) {
        const int jt = q >> 2, kc = q & 3, buf = q & 1;
#pragma unroll
        for (int t = 0; t < 8; t++) {
            int i = tid + t * 256;
            int s = i >> 10, r = (i >> 3) & 127, c = i & 7;
            const __nv_bfloat16* g = (s ? g_elo : g_ehi)
                + (size_t)(jt * 128 + r) * DIMS + kc * 64 + c * 8;
            cp_async16(sb + SM_B + (buf * 2 + s) * 16384 + r * 128 + ((c ^ (r & 7)) << 4), g);
        }
        CP_COMMIT();
    };
    stageB(0);

    const int arow_base = wm * 64 + (l & 15);   // + mt*16
    const int ach = l >> 4;
    const int brow_base = wn * 32 + (l & 7);    // + nt*8
    const int bch = (l >> 3) & 1;

    float acc[4][4][4];
    float sv0[8], sv1[8]; int sj0[8], sj1[8];
#pragma unroll
    for (int s = 0; s < 8; s++) { sv0[s] = CUDART_INF_F; sv1[s] = CUDART_INF_F; sj0[s] = 0; sj1[s] = 0; }

    for (int q = 0; q < 256; q++) {
        const int jt = q >> 2, kc = q & 3, buf = q & 1;
        if (q + 1 < 256) { stageB(q + 1); CP_WAIT1(); } else { CP_WAIT0(); }
        __syncthreads();

        if (kc == 0) {
#pragma unroll
            for (int mt = 0; mt < 4; mt++)
#pragma unroll
                for (int nt = 0; nt < 4; nt++)
#pragma unroll
                    for (int e = 0; e < 4; e++) acc[mt][nt][e] = 0.0f;
        }

#pragma unroll
        for (int ks = 0; ks < 4; ks++) {
            const int kb = ks * 2;
            uint32_t bhi[4][2], blo[4][2];
#pragma unroll
            for (int nt = 0; nt < 4; nt++) {
                int row = brow_base + nt * 8;
                uint32_t a0 = sb + SM_B + (buf * 2) * 16384 + row * 128
                              + (((kb + bch) ^ (row & 7)) << 4);
                ldsm_x2(bhi[nt], a0);
                ldsm_x2(blo[nt], a0 + 16384);
            }
#pragma unroll
            for (int mt = 0; mt < 4; mt++) {
                int row = arow_base + mt * 16;
                uint32_t aa = sb + SM_A + kc * 16384 + row * 128
                              + (((kb + ach) ^ (row & 7)) << 4);
                uint32_t a_hi[4], a_lo[4];
                ldsm_x4(a_hi, aa);
                ldsm_x4(a_lo, aa + 65536);
#pragma unroll
                for (int nt = 0; nt < 4; nt++) {
                    mma16816(acc[mt][nt], a_hi, bhi[nt]);
                    mma16816(acc[mt][nt], a_hi, blo[nt]);
                    mma16816(acc[mt][nt], a_lo, bhi[nt]);
                }
            }
        }
        __syncthreads();

        if (kc == 3) {
            // distances + lane-local running top-2 over this jt tile
#pragma unroll
            for (int nt = 0; nt < 4; nt++) {
                int cbase = jt * 128 + wn * 32 + nt * 8 + 2 * (l & 3);
                float2 en = __ldg((const float2*)&g_enorm[cbase]);
#pragma unroll
                for (int mt = 0; mt < 4; mt++) {
                    float d0 = fmaf(-2.0f, acc[mt][nt][0], en.x);
                    float d1 = fmaf(-2.0f, acc[mt][nt][1], en.y);
                    float d2 = fmaf(-2.0f, acc[mt][nt][2], en.x);
                    float d3 = fmaf(-2.0f, acc[mt][nt][3], en.y);
                    const int s0 = mt * 2, s1 = mt * 2 + 1;
                    if (d0 < sv0[s0]) { sv1[s0] = sv0[s0]; sj1[s0] = sj0[s0]; sv0[s0] = d0; sj0[s0] = cbase; }
                    else if (d0 < sv1[s0]) { sv1[s0] = d0; sj1[s0] = cbase; }
                    if (d1 < sv0[s0]) { sv1[s0] = sv0[s0]; sj1[s0] = sj0[s0]; sv0[s0] = d1; sj0[s0] = cbase + 1; }
                    else if (d1 < sv1[s0]) { sv1[s0] = d1; sj1[s0] = cbase + 1; }
                    if (d2 < sv0[s1]) { sv1[s1] = sv0[s1]; sj1[s1] = sj0[s1]; sv0[s1] = d2; sj0[s1] = cbase; }
                    else if (d2 < sv1[s1]) { sv1[s1] = d2; sj1[s1] = cbase; }
                    if (d3 < sv0[s1]) { sv1[s1] = sv0[s1]; sj1[s1] = sj0[s1]; sv0[s1] = d3; sj0[s1] = cbase + 1; }
                    else if (d3 < sv1[s1]) { sv1[s1] = d3; sj1[s1] = cbase + 1; }
                }
            }
        }
    }

    // cross-lane merge (4 lanes share a row), stash per-warp result in smem
    __syncthreads();
#pragma unroll
    for (int mt = 0; mt < 4; mt++) {
#pragma unroll
        for (int h = 0; h < 2; h++) {
            int s = mt * 2 + h;
            float v0 = sv0[s], v1 = sv1[s]; int j0 = sj0[s], j1 = sj1[s];
#pragma unroll
            for (int o = 1; o <= 2; o <<= 1) {
                float w0 = __shfl_xor_sync(0xffffffffu, v0, o);
                int   i0 = __shfl_xor_sync(0xffffffffu, j0, o);
                float w1 = __shfl_xor_sync(0xffffffffu, v1, o);
                int   i1 = __shfl_xor_sync(0xffffffffu, j1, o);
                top2_merge(v0, j0, v1, j1, w0, i0, w1, i1);
            }
            if ((l & 3) == 0) {
                int rl = wm * 64 + mt * 16 + h * 8 + (l >> 2);
                float4 v = make_float4(v0, v1, __int_as_float(j0), __int_as_float(j1));
                ((float4*)(smem + SM_RED))[rl * 4 + wn] = v;
            }
        }
    }
    __syncthreads();

    // merge the 4 n-warps per row, write final top-2
    if (tid < 128) {
        float4 a = ((const float4*)(smem + SM_RED))[tid * 4 + 0];
        float v0 = a.x, v1 = a.y; int j0 = __float_as_int(a.z), j1 = __float_as_int(a.w);
#pragma unroll
        for (int w = 1; w < 4; w++) {
            float4 b = ((const float4*)(smem + SM_RED))[tid * 4 + w];
            top2_merge(v0, j0, v1, j1, b.x, __float_as_int(b.z), b.y, __float_as_int(b.w));
        }
        int row = row0 + tid;
        g_arg2[2 * row]     = j0;
        g_arg2[2 * row + 1] = j1;
    }
}

// ---------------------------------------------------------------------------
// D: exact fp32 rescore of top-2, then gather quantize, diff, segment sums.
// ---------------------------------------------------------------------------
__global__ __launch_bounds__(256) void k_gather(
    const float* __restrict__ z, const float* __restrict__ E,
    float* __restrict__ out)
{
    __shared__ float warpsum[8];
    const int warp = threadIdx.x >> 5, lane = threadIdx.x & 31;
    const int r = blockIdx.x * 8 + warp;
    const int c0 = g_arg2[2 * r], c1 = g_arg2[2 * r + 1];

    float zv[8], e0[8], e1[8];
    float dot0 = 0.0f, dot1 = 0.0f;
#pragma unroll
    for (int it = 0; it < 8; it++) {
        int d = lane + it * 32;
        zv[it] = z[(size_t)r * DIMS + d];
        e0[it] = E[(size_t)d * NEMB + c0];
        e1[it] = E[(size_t)d * NEMB + c1];
        dot0 = fmaf(zv[it], e0[it], dot0);
        dot1 = fmaf(zv[it], e1[it], dot1);
    }
#pragma unroll
    for (int o = 16; o; o >>= 1) {
        dot0 += __shfl_xor_sync(0xffffffffu, dot0, o);
        dot1 += __shfl_xor_sync(0xffffffffu, dot1, o);
    }
    float d0 = fmaf(-2.0f, dot0, g_enorm[c0]);
    float d1 = fmaf(-2.0f, dot1, g_enorm[c1]);
    bool take1 = (d1 < d0) || (d1 == d0 && c1 < c0);
    int j = take1 ? c1 : c0;

    float ss = 0.0f;
#pragma unroll
    for (int it = 0; it < 8; it++) {
        int d = lane + it * 32;
        float e = take1 ? e1[it] : e0[it];
        float qd = e - zv[it];
        out[OFF_Q + (size_t)r * DIMS + d] = zv[it] + qd;
        ss = fmaf(qd, qd, ss);
        atomicAdd(&out[OFF_AVG + (size_t)d * NEMB + j], 0.01f * zv[it]);
    }
    if (lane == 0) {
        atomicAdd(&g_count[j], 1);
        out[OFF_IND + r] = (float)j;
    }
#pragma unroll
    for (int o = 16; o; o >>= 1) ss += __shfl_down_sync(0xffffffffu, ss, o);
    if (lane == 0) warpsum[warp] = ss;
    __syncthreads();
    if (threadIdx.x == 0) {
        float t = 0.0f;
#pragma unroll
        for (int w = 0; w < 8; w++) t += warpsum[w];
        atomicAdd(&out[OFF_DIFF], t);
    }
}

// ---------------------------------------------------------------------------
// E: new_cluster_size + global n reduction
// ---------------------------------------------------------------------------
__global__ void k_ncs(const float* __restrict__ cs, float* __restrict__ out) {
    __shared__ float sh[256];
    int j = blockIdx.x * 256 + threadIdx.x;
    float v = cs[j] * 0.99f + 0.01f * (float)g_count[j];
    out[OFF_NCS + j] = v;
    sh[threadIdx.x] = v;
    __syncthreads();
    for (int s = 128; s; s >>= 1) {
        if (threadIdx.x < s) sh[threadIdx.x] += sh[threadIdx.x + s];
        __syncthreads();
    }
    if (threadIdx.x == 0) atomicAdd(&g_n, sh[0]);
}

// ---------------------------------------------------------------------------
// F: new_embedding = avg / smoothed; finalize diff mean
// ---------------------------------------------------------------------------
__global__ void k_final(float* __restrict__ out) {
    int i = blockIdx.x * blockDim.x + threadIdx.x;
    if (i == 0) out[OFF_DIFF] *= (1.0f / 4194304.0f);
    if (i >= DIMS * NEMB) return;
    float n = g_n;
    int j = i & (NEMB - 1);
    float ncs = out[OFF_NCS + j];
    float smoothed = (ncs + 1e-5f) / (n + (float)NEMB * 1e-5f) * n;
    out[OFF_EMB + i] = out[OFF_AVG + i] / smoothed;
}

// ---------------------------------------------------------------------------
extern "C" void kernel_launch(void* const* d_in, const int* in_sizes, int n_in,
                              void* d_out, int out_size) {
    const float* z    = (const float*)d_in[0];   // [16,32,32,256]
    const float* E    = (const float*)d_in[1];   // [256, 8192]
    const float* cs   = (const float*)d_in[2];   // [8192]
    const float* eavg = (const float*)d_in[3];   // [256, 8192]
    float* out = (float*)d_out;

    static int cfg_done = 0;
    if (!cfg_done) {
        cudaFuncSetAttribute(k_argmin_mma,
                             cudaFuncAttributeMaxDynamicSharedMemorySize, SMEM_TOTAL);
        cfg_done = 1;
    }

    k_init    <<<(DIMS * NEMB + 255) / 256, 256>>>(eavg, out);
    k_enorm   <<<NEMB / 256, 256>>>(E);
    k_split_z <<<NROWS * DIMS / 256, 256>>>(z);
    {
        dim3 g(NEMB / 32, DIMS / 32), b(32, 8);
        k_split_eT<<<g, b>>>(E);
    }
    k_argmin_mma<<<NROWS / 128, 256, SMEM_TOTAL>>>();
    k_gather  <<<NROWS / 8, 256>>>(z, E, out);
    k_ncs     <<<NEMB / 256, 256>>>(cs, out);
    k_final   <<<(DIMS * NEMB + 255) / 256, 256>>>(out);
}